// round 2
// baseline (speedup 1.0000x reference)
#include <cuda_runtime.h>

#define BATCH 32
#define SEQ   512
#define DM    512
#define HID   512
#define G4    2048
#define NCTA  128
#define KT    64

typedef unsigned long long u64;

// ---------------- scratch (static device arrays; no allocations) ----------------
__device__ float g_zx0[(size_t)BATCH * SEQ * G4];   // precomputed X @ Wk0 + b0  (134MB)
__device__ float g_h0[2][BATCH * HID];              // layer0 h, double buffered by step parity
__device__ float g_h1[2][BATCH * HID];              // layer1 h, double buffered
__device__ float g_c0[BATCH * HID];                 // cell states (in-place, column-owned)
__device__ float g_c1[BATCH * HID];

// ---------------- packed f32x2 helpers ----------------
__device__ __forceinline__ u64 pk(float lo, float hi) {
    u64 r; asm("mov.b64 %0, {%1,%2};" : "=l"(r) : "f"(lo), "f"(hi)); return r;
}
__device__ __forceinline__ float2 upk(u64 v) {
    float2 r; asm("mov.b64 {%0,%1}, %2;" : "=f"(r.x), "=f"(r.y) : "l"(v)); return r;
}
__device__ __forceinline__ void fma2(u64 &acc, u64 a, u64 b) {
    asm("fma.rn.f32x2 %0, %1, %2, %0;" : "+l"(acc) : "l"(a), "l"(b));
}

__device__ __forceinline__ float sigf(float x)  { return 1.f / (1.f + __expf(-x)); }
__device__ __forceinline__ float tanhfa(float x){ return 2.f / (1.f + __expf(-2.f * x)) - 1.f; }

// ---------------- init: zero recurrent state (every graph replay) ----------------
__global__ void init_kernel() {
    int i = blockIdx.x * blockDim.x + threadIdx.x;
    if (i < BATCH * HID) {
        g_c0[i] = 0.f; g_c1[i] = 0.f;
        g_h0[0][i] = 0.f; g_h0[1][i] = 0.f;
        g_h1[0][i] = 0.f; g_h1[1][i] = 0.f;
    }
}

// ---------------- embedding gather: one block per (b,s) row ----------------
__global__ void embed_kernel(const int* __restrict__ src,
                             const float* __restrict__ emb,
                             float* __restrict__ oe) {
    int bs = blockIdx.x;
    int tok = src[bs];
    const float4* er = (const float4*)(emb + (size_t)tok * DM);
    float4* orow = (float4*)(oe + (size_t)bs * DM);
    orow[threadIdx.x] = er[threadIdx.x];  // 128 threads x float4 = 512 floats
}

// ---------------- big GEMM: Zx0 = X @ Wk0 + b0  (16384 x 2048 x 512) ----------------
// BM=64, BN=64, BK=16, 256 threads, thread tile 4x4 using packed f32x2 along M.
__global__ __launch_bounds__(256) void gemm_zx0(const float* __restrict__ X,
                                                const float* __restrict__ Wk,
                                                const float* __restrict__ bias) {
    __shared__ float As[16][64];   // [k][m]
    __shared__ float Bs[16][64];   // [k][n]
    const int bm = blockIdx.y * 64;
    const int bn = blockIdx.x * 64;
    const int tid = threadIdx.x;
    const int tx = tid & 15, ty = tid >> 4;

    u64 acc[2][4];
#pragma unroll
    for (int p = 0; p < 2; p++)
#pragma unroll
        for (int q = 0; q < 4; q++) acc[p][q] = 0ull;

    const int lm  = tid >> 2, lk  = (tid & 3) * 4;   // A loader
    const int lbk = tid >> 4, lbn = (tid & 15) * 4;  // B loader

    for (int k0 = 0; k0 < DM; k0 += 16) {
        float4 av = *(const float4*)(X + (size_t)(bm + lm) * DM + k0 + lk);
        As[lk + 0][lm] = av.x; As[lk + 1][lm] = av.y;
        As[lk + 2][lm] = av.z; As[lk + 3][lm] = av.w;
        float4 bv = *(const float4*)(Wk + (size_t)(k0 + lbk) * G4 + bn + lbn);
        *(float4*)&Bs[lbk][lbn] = bv;
        __syncthreads();
#pragma unroll
        for (int kk = 0; kk < 16; kk++) {
            u64 a0 = *(const u64*)&As[kk][ty * 4];
            u64 a1 = *(const u64*)&As[kk][ty * 4 + 2];
            float4 bq = *(const float4*)&Bs[kk][tx * 4];
            u64 b0 = pk(bq.x, bq.x), b1 = pk(bq.y, bq.y);
            u64 b2 = pk(bq.z, bq.z), b3 = pk(bq.w, bq.w);
            fma2(acc[0][0], a0, b0); fma2(acc[0][1], a0, b1);
            fma2(acc[0][2], a0, b2); fma2(acc[0][3], a0, b3);
            fma2(acc[1][0], a1, b0); fma2(acc[1][1], a1, b1);
            fma2(acc[1][2], a1, b2); fma2(acc[1][3], a1, b3);
        }
        __syncthreads();
    }
#pragma unroll
    for (int q = 0; q < 4; q++) {
        int nn = bn + tx * 4 + q;
        float bb = bias[nn];
        float2 v0 = upk(acc[0][q]);
        float2 v1 = upk(acc[1][q]);
        size_t base = (size_t)(bm + ty * 4) * G4 + nn;
        g_zx0[base]                  = v0.x + bb;
        g_zx0[base + G4]             = v0.y + bb;
        g_zx0[base + 2 * (size_t)G4] = v1.x + bb;
        g_zx0[base + 3 * (size_t)G4] = v1.y + bb;
    }
}

// ---------------- per-step kernel (layer-skewed) ----------------
// kernel j: Phase A = layer0 step t0=j  (if j<SEQ)
//           Phase B = layer1 step t1=j-1 (if j>=1)
// 128 CTAs x 256 threads. Each CTA owns 4 hidden units (all 4 gates).
// Threads split into 2 K-halves of 128; within a half: 16 cols x 8 batch-groups(x4b).
__global__ __launch_bounds__(256) void step_kernel(int j,
                                                   const float* __restrict__ Wk,
                                                   const float* __restrict__ Wr,
                                                   const float* __restrict__ bias,
                                                   float* __restrict__ out) {
    __shared__ float hs[2][KT * 34];      // h tile per k-half, stride 34 (pairs 8B aligned)
    __shared__ float ws[2][KT * 16];      // W tile per k-half
    __shared__ float zsh[2][16 * 33];     // partial z per k-half

    const int tid = threadIdx.x;
    const int cid = blockIdx.x;
    const int rb = j & 1, wb = rb ^ 1;
    const int kh = tid >> 7;              // k-half 0/1
    const int t7 = tid & 127;
    const int c_local = t7 & 15;          // 0..15 : gate*4 + unit
    const int bp = t7 >> 4;               // 0..7  : batch group of 4
    const int u0 = cid * 4;
    const int ncol = (c_local >> 2) * 512 + u0 + (c_local & 3);
    float* hsk = hs[kh];
    float* wsk = ws[kh];

    // ================= Phase A: layer 0 =================
    if (j < SEQ) {
        const float* h0r = g_h0[rb];
        u64 acc0 = 0ull, acc1 = 0ull;
#pragma unroll 1
        for (int p = 0; p < 4; p++) {
            const int k0 = kh * 256 + p * KT;
            for (int e = t7; e < KT * 32; e += 128) {
                int b = e >> 6, kk = e & (KT - 1);
                hsk[kk * 34 + b] = h0r[b * HID + k0 + kk];
            }
            for (int e = t7; e < KT * 16; e += 128) {
                int kk = e >> 4, c = e & 15;
                int nn = (c >> 2) * 512 + u0 + (c & 3);
                wsk[kk * 16 + c] = Wr[(size_t)(k0 + kk) * G4 + nn];  // layer0 Wr
            }
            __syncthreads();
#pragma unroll 8
            for (int kk = 0; kk < KT; kk++) {
                float w = wsk[kk * 16 + c_local];
                u64 w2 = pk(w, w);
                u64 ha = *(const u64*)&hsk[kk * 34 + 4 * bp];
                u64 hb = *(const u64*)&hsk[kk * 34 + 4 * bp + 2];
                fma2(acc0, ha, w2);
                fma2(acc1, hb, w2);
            }
            __syncthreads();
        }
        float2 a0 = upk(acc0), a1 = upk(acc1);
        float* zr = &zsh[kh][c_local * 33 + 4 * bp];
        zr[0] = a0.x; zr[1] = a0.y; zr[2] = a1.x; zr[3] = a1.y;
        __syncthreads();
        if (tid < 128) {
            int b = tid & 31, ul = tid >> 5;
            const float* zx = &g_zx0[((size_t)b * SEQ + j) * G4 + u0 + ul];
            float zi = zsh[0][(0 + ul) * 33 + b]  + zsh[1][(0 + ul) * 33 + b]  + zx[0];
            float zf = zsh[0][(4 + ul) * 33 + b]  + zsh[1][(4 + ul) * 33 + b]  + zx[512];
            float zg = zsh[0][(8 + ul) * 33 + b]  + zsh[1][(8 + ul) * 33 + b]  + zx[1024];
            float zo = zsh[0][(12 + ul) * 33 + b] + zsh[1][(12 + ul) * 33 + b] + zx[1536];
            int idx = b * HID + u0 + ul;
            float ig = sigf(zi), fg = sigf(zf), gg = tanhfa(zg), og = sigf(zo);
            float cnew = fg * g_c0[idx] + ig * gg;
            float hnew = og * tanhfa(cnew);
            g_c0[idx] = cnew;
            g_h0[wb][idx] = hnew;
        }
    }
    __syncthreads();

    // ================= Phase B: layer 1 (step j-1) =================
    if (j >= 1) {
        const int t1 = j - 1;
        // K halves map exactly onto the two contributions:
        //   half 0: x (= h0 at step t1, in read buffer) @ Wk1
        //   half 1: h1_prev @ Wr1
        const float* hsrc = kh ? g_h1[rb] : g_h0[rb];
        const float* W    = kh ? (Wr + (size_t)HID * G4) : (Wk + (size_t)HID * G4);
        u64 acc0 = 0ull, acc1 = 0ull;
#pragma unroll 1
        for (int p = 0; p < 8; p++) {
            const int k0 = p * KT;
            for (int e = t7; e < KT * 32; e += 128) {
                int b = e >> 6, kk = e & (KT - 1);
                hsk[kk * 34 + b] = hsrc[b * HID + k0 + kk];
            }
            for (int e = t7; e < KT * 16; e += 128) {
                int kk = e >> 4, c = e & 15;
                int nn = (c >> 2) * 512 + u0 + (c & 3);
                wsk[kk * 16 + c] = W[(size_t)(k0 + kk) * G4 + nn];
            }
            __syncthreads();
#pragma unroll 8
            for (int kk = 0; kk < KT; kk++) {
                float w = wsk[kk * 16 + c_local];
                u64 w2 = pk(w, w);
                u64 ha = *(const u64*)&hsk[kk * 34 + 4 * bp];
                u64 hb = *(const u64*)&hsk[kk * 34 + 4 * bp + 2];
                fma2(acc0, ha, w2);
                fma2(acc1, hb, w2);
            }
            __syncthreads();
        }
        float2 a0 = upk(acc0), a1 = upk(acc1);
        float* zr = &zsh[kh][c_local * 33 + 4 * bp];
        zr[0] = a0.x; zr[1] = a0.y; zr[2] = a1.x; zr[3] = a1.y;
        __syncthreads();
        if (tid < 128) {
            int b = tid & 31, ul = tid >> 5;
            int u = u0 + ul;
            float zi = zsh[0][(0 + ul) * 33 + b]  + zsh[1][(0 + ul) * 33 + b]  + bias[G4 + u];
            float zf = zsh[0][(4 + ul) * 33 + b]  + zsh[1][(4 + ul) * 33 + b]  + bias[G4 + 512 + u];
            float zg = zsh[0][(8 + ul) * 33 + b]  + zsh[1][(8 + ul) * 33 + b]  + bias[G4 + 1024 + u];
            float zo = zsh[0][(12 + ul) * 33 + b] + zsh[1][(12 + ul) * 33 + b] + bias[G4 + 1536 + u];
            int idx = b * HID + u;
            float ig = sigf(zi), fg = sigf(zf), gg = tanhfa(zg), og = sigf(zo);
            float cnew = fg * g_c1[idx] + ig * gg;
            float hnew = og * tanhfa(cnew);
            g_c1[idx] = cnew;
            g_h1[wb][idx] = hnew;
            out[(size_t)b * SEQ * HID + (size_t)t1 * HID + u] = hnew;
        }
    }
}

// ---------------- launch ----------------
extern "C" void kernel_launch(void* const* d_in, const int* in_sizes, int n_in,
                              void* d_out, int out_size) {
    const int*   src  = (const int*)  d_in[0];
    // d_in[1] = source_len (unused by the reference computation)
    const float* emb  = (const float*)d_in[2];
    const float* Wk   = (const float*)d_in[3];
    const float* Wr   = (const float*)d_in[4];
    const float* bias = (const float*)d_in[5];
    float* out = (float*)d_out;
    float* out_emb = out + (size_t)BATCH * SEQ * HID;   // second tuple element

    // reset recurrent state (graph is replayed many times)
    init_kernel<<<64, 256>>>();

    // embedding gather -> also the second output
    embed_kernel<<<BATCH * SEQ, 128>>>(src, emb, out_emb);

    // precompute layer0 input projection for all timesteps
    gemm_zx0<<<dim3(G4 / 64, (BATCH * SEQ) / 64), 256>>>(out_emb, Wk, bias);

    // layer-skewed recurrence: 513 step kernels
    for (int j = 0; j <= SEQ; j++) {
        step_kernel<<<NCTA, 256>>>(j, Wk, Wr, bias, out);
    }
}

// round 3
// speedup vs baseline: 2.7866x; 2.7866x over previous
#include <cuda_runtime.h>

#define BATCH 32
#define SEQ   512
#define HID   512
#define G4    2048
#define NCTA  128
#define TPB   256
#define RSTR  516   // smem row stride in floats (129 x 16B chunks)

typedef unsigned long long u64;

// ---------------- static device scratch ----------------
__device__ float g_zx0[(size_t)BATCH * SEQ * G4];   // X @ Wk0 + b0
__device__ float g_h0[2][BATCH * HID];
__device__ float g_h1[2][BATCH * HID];
__device__ float g_c0[BATCH * HID];
__device__ float g_c1[BATCH * HID];
__device__ unsigned g_count;

// ---------------- packed f32x2 helpers ----------------
__device__ __forceinline__ u64 pk(float lo, float hi) {
    u64 r; asm("mov.b64 %0, {%1,%2};" : "=l"(r) : "f"(lo), "f"(hi)); return r;
}
__device__ __forceinline__ float2 upk(u64 v) {
    float2 r; asm("mov.b64 {%0,%1}, %2;" : "=f"(r.x), "=f"(r.y) : "l"(v)); return r;
}
__device__ __forceinline__ void fma2(u64 &acc, u64 a, u64 b) {
    asm("fma.rn.f32x2 %0, %1, %2, %0;" : "+l"(acc) : "l"(a), "l"(b));
}
__device__ __forceinline__ u64 add2(u64 a, u64 b) {
    u64 r; asm("add.rn.f32x2 %0, %1, %2;" : "=l"(r) : "l"(a), "l"(b)); return r;
}

__device__ __forceinline__ float sigf(float x)  { return 1.f / (1.f + __expf(-x)); }
__device__ __forceinline__ float tanhfa(float x){ return 2.f / (1.f + __expf(-2.f * x)) - 1.f; }

// ---------------- init ----------------
__global__ void init_kernel() {
    int i = blockIdx.x * blockDim.x + threadIdx.x;
    if (i == 0) g_count = 0u;
    if (i < BATCH * HID) {
        g_c0[i] = 0.f; g_c1[i] = 0.f;
        g_h0[0][i] = 0.f; g_h0[1][i] = 0.f;
        g_h1[0][i] = 0.f; g_h1[1][i] = 0.f;
    }
}

// ---------------- embedding gather ----------------
__global__ void embed_kernel(const int* __restrict__ src,
                             const float* __restrict__ emb,
                             float* __restrict__ oe) {
    int bs = blockIdx.x;
    int tok = src[bs];
    const float4* er = (const float4*)(emb + (size_t)tok * HID);
    float4* orow = (float4*)(oe + (size_t)bs * HID);
    orow[threadIdx.x] = er[threadIdx.x];
}

// ---------------- precompute GEMM: Zx0 = X @ Wk0 + b0  (16384 x 2048 x 512) ----------------
// BM=128, BN=64, BK=16; 256 threads; thread tile 8(M, as 4 f32x2) x 4(N).
__global__ __launch_bounds__(256) void gemm_zx0(const float* __restrict__ X,
                                                const float* __restrict__ Wk,
                                                const float* __restrict__ bias) {
    __shared__ float As[16][128];
    __shared__ float Bs[16][64];
    const int bm = blockIdx.y * 128;
    const int bn = blockIdx.x * 64;
    const int tid = threadIdx.x;
    const int tx = tid & 15, ty = tid >> 4;

    u64 acc[4][4];
#pragma unroll
    for (int p = 0; p < 4; p++)
#pragma unroll
        for (int q = 0; q < 4; q++) acc[p][q] = 0ull;

    for (int k0 = 0; k0 < 512; k0 += 16) {
#pragma unroll
        for (int r = 0; r < 2; r++) {
            int i = tid + 256 * r;
            int m = i >> 2, kq = (i & 3) * 4;
            float4 v = *(const float4*)(X + (size_t)(bm + m) * 512 + k0 + kq);
            As[kq + 0][m] = v.x; As[kq + 1][m] = v.y;
            As[kq + 2][m] = v.z; As[kq + 3][m] = v.w;
        }
        {
            int k = tid >> 4, n4 = (tid & 15) * 4;
            *(float4*)&Bs[k][n4] = *(const float4*)(Wk + (size_t)(k0 + k) * G4 + bn + n4);
        }
        __syncthreads();
#pragma unroll
        for (int kk = 0; kk < 16; kk++) {
            u64 a0 = *(const u64*)&As[kk][ty * 8 + 0];
            u64 a1 = *(const u64*)&As[kk][ty * 8 + 2];
            u64 a2 = *(const u64*)&As[kk][ty * 8 + 4];
            u64 a3 = *(const u64*)&As[kk][ty * 8 + 6];
            float4 bv = *(const float4*)&Bs[kk][tx * 4];
            u64 b0 = pk(bv.x, bv.x), b1 = pk(bv.y, bv.y);
            u64 b2 = pk(bv.z, bv.z), b3 = pk(bv.w, bv.w);
            fma2(acc[0][0], a0, b0); fma2(acc[0][1], a0, b1); fma2(acc[0][2], a0, b2); fma2(acc[0][3], a0, b3);
            fma2(acc[1][0], a1, b0); fma2(acc[1][1], a1, b1); fma2(acc[1][2], a1, b2); fma2(acc[1][3], a1, b3);
            fma2(acc[2][0], a2, b0); fma2(acc[2][1], a2, b1); fma2(acc[2][2], a2, b2); fma2(acc[2][3], a2, b3);
            fma2(acc[3][0], a3, b0); fma2(acc[3][1], a3, b1); fma2(acc[3][2], a3, b2); fma2(acc[3][3], a3, b3);
        }
        __syncthreads();
    }
#pragma unroll
    for (int p = 0; p < 4; p++) {
#pragma unroll
        for (int q = 0; q < 4; q++) {
            int m0 = bm + ty * 8 + 2 * p;
            int n = bn + tx * 4 + q;
            float bb = bias[n];
            float2 v = upk(acc[p][q]);
            g_zx0[(size_t)m0 * G4 + n]       = v.x + bb;
            g_zx0[(size_t)(m0 + 1) * G4 + n] = v.y + bb;
        }
    }
}

// ---------------- persistent recurrence kernel helpers ----------------
__device__ __forceinline__ void accum_half(u64* acc, const float* hb, const float* wm,
                                           int s, int cg, int b0) {
    const float* hp0 = hb + (b0 + 0) * RSTR;
    const float* hp1 = hb + (b0 + 1) * RSTR;
    const float* hp2 = hb + (b0 + 2) * RSTR;
    const float* hp3 = hb + (b0 + 3) * RSTR;
    const float* wp0 = wm + (cg     ) * RSTR;
    const float* wp1 = wm + (cg +  4) * RSTR;
    const float* wp2 = wm + (cg +  8) * RSTR;
    const float* wp3 = wm + (cg + 12) * RSTR;
#pragma unroll
    for (int ii = 0; ii < 16; ii++) {
        const int fo = (((s << 4) | (ii ^ s)) << 2);
        ulonglong2 h0 = *(const ulonglong2*)(hp0 + fo);
        ulonglong2 h1 = *(const ulonglong2*)(hp1 + fo);
        ulonglong2 h2 = *(const ulonglong2*)(hp2 + fo);
        ulonglong2 h3 = *(const ulonglong2*)(hp3 + fo);
        ulonglong2 w0 = *(const ulonglong2*)(wp0 + fo);
        ulonglong2 w1 = *(const ulonglong2*)(wp1 + fo);
        ulonglong2 w2 = *(const ulonglong2*)(wp2 + fo);
        ulonglong2 w3 = *(const ulonglong2*)(wp3 + fo);
        fma2(acc[ 0], w0.x, h0.x); fma2(acc[ 0], w0.y, h0.y);
        fma2(acc[ 1], w0.x, h1.x); fma2(acc[ 1], w0.y, h1.y);
        fma2(acc[ 2], w0.x, h2.x); fma2(acc[ 2], w0.y, h2.y);
        fma2(acc[ 3], w0.x, h3.x); fma2(acc[ 3], w0.y, h3.y);
        fma2(acc[ 4], w1.x, h0.x); fma2(acc[ 4], w1.y, h0.y);
        fma2(acc[ 5], w1.x, h1.x); fma2(acc[ 5], w1.y, h1.y);
        fma2(acc[ 6], w1.x, h2.x); fma2(acc[ 6], w1.y, h2.y);
        fma2(acc[ 7], w1.x, h3.x); fma2(acc[ 7], w1.y, h3.y);
        fma2(acc[ 8], w2.x, h0.x); fma2(acc[ 8], w2.y, h0.y);
        fma2(acc[ 9], w2.x, h1.x); fma2(acc[ 9], w2.y, h1.y);
        fma2(acc[10], w2.x, h2.x); fma2(acc[10], w2.y, h2.y);
        fma2(acc[11], w2.x, h3.x); fma2(acc[11], w2.y, h3.y);
        fma2(acc[12], w3.x, h0.x); fma2(acc[12], w3.y, h0.y);
        fma2(acc[13], w3.x, h1.x); fma2(acc[13], w3.y, h1.y);
        fma2(acc[14], w3.x, h2.x); fma2(acc[14], w3.y, h2.y);
        fma2(acc[15], w3.x, h3.x); fma2(acc[15], w3.y, h3.y);
    }
}

__device__ __forceinline__ void dumpacc(u64* part, const u64* acc, int s, int cg, int b0) {
#pragma unroll
    for (int ci = 0; ci < 4; ci++)
#pragma unroll
        for (int bi = 0; bi < 4; bi++)
            part[((((cg + 4 * ci) << 5) | (b0 + bi)) << 3) + s] = acc[ci * 4 + bi];
}

__device__ __forceinline__ float redcell(const u64* part, int e) {
    const u64* p = part + (e << 3);
    u64 r = add2(add2(add2(p[0], p[1]), add2(p[2], p[3])),
                 add2(add2(p[4], p[5]), add2(p[6], p[7])));
    float2 v = upk(r);
    return v.x + v.y;
}

__device__ __forceinline__ void stage_h(float* hb, const float* __restrict__ src, int tid) {
#pragma unroll
    for (int i = 0; i < 16; i++) {
        int gci = tid + TPB * i;              // 4096 16B chunks total
        int b = gci >> 7, cc = gci & 127;
        int pc = cc ^ ((cc >> 4) & 7);
        *(float4*)(hb + b * RSTR + pc * 4) = *(const float4*)(src + gci * 4);
    }
}

// ---------------- persistent kernel: all 512 steps, 2 layers, skewed ----------------
__global__ __launch_bounds__(TPB) void persist_kernel(const float* __restrict__ Wk,
                                                      const float* __restrict__ Wr,
                                                      const float* __restrict__ bias,
                                                      float* __restrict__ out) {
    extern __shared__ float smf[];
    float* wbm = smf;                        // 48 rows x 516 floats (3 matrices x 16 cols)
    float* hb  = smf + 24768;                // 32 rows x 516
    u64*  part = (u64*)(smf + 41280);        // 512 cells x 8 ksegs
    float* zb  = smf + 49472;                // 16 x 33

    const int tid = threadIdx.x;
    const int cid = blockIdx.x;
    const int u0 = cid * 4;
    const int s  = tid & 7;
    const int cg = (tid >> 3) & 3;
    const int b0 = (tid >> 5) * 4;

    // ---- load weight slices once (transposed + k-swizzled) ----
    const float* wsrc0 = Wr;                          // layer0 Wr
    const float* wsrc1 = Wk + (size_t)HID * G4;       // layer1 Wk
    const float* wsrc2 = Wr + (size_t)HID * G4;       // layer1 Wr
    const float* wsrcs[3] = { wsrc0, wsrc1, wsrc2 };
#pragma unroll
    for (int m = 0; m < 3; m++) {
        float* dst = wbm + m * 16 * RSTR;
        for (int i = 0; i < 8; i++) {
            int t2 = tid + TPB * i;
            int g = t2 & 3, k = t2 >> 2;
            float4 v = *(const float4*)(wsrcs[m] + (size_t)k * G4 + g * HID + u0);
            int cc = k >> 2, ki = k & 3;
            int pc = cc ^ ((cc >> 4) & 7);
            int fo = pc * 4 + ki;
            dst[(g * 4 + 0) * RSTR + fo] = v.x;
            dst[(g * 4 + 1) * RSTR + fo] = v.y;
            dst[(g * 4 + 2) * RSTR + fo] = v.z;
            dst[(g * 4 + 3) * RSTR + fo] = v.w;
        }
    }

    // per-thread reducer constants (cells e0 = tid, e1 = tid + 256)
    const int e0 = tid, e1 = tid + 256;
    const int rc0 = e0 >> 5, rb0 = e0 & 31;
    const int rc1 = e1 >> 5, rb1 = e1 & 31;
    const int col0 = (rc0 >> 2) * HID + u0 + (rc0 & 3);
    const int col1 = (rc1 >> 2) * HID + u0 + (rc1 & 3);
    const float biasB0 = bias[G4 + col0];
    const float biasB1 = bias[G4 + col1];
    // gate-thread constants (tid < 128)
    const int gb = tid & 31, gul = (tid >> 5) & 3;
    const int gidx = gb * HID + u0 + gul;
    __syncthreads();

    for (int j = 0; j <= SEQ; j++) {
        const int rbuf = j & 1, wb2 = rbuf ^ 1;

        stage_h(hb, g_h0[rbuf], tid);
        float zxa0 = 0.f, zxa1 = 0.f;
        if (j < SEQ) {
            zxa0 = g_zx0[((size_t)(rb0 * SEQ + j)) * G4 + col0];
            zxa1 = g_zx0[((size_t)(rb1 * SEQ + j)) * G4 + col1];
        }
        __syncthreads();                                   // S1: hbuf=h0 ready

        u64 accA[16], accB[16];
#pragma unroll
        for (int q = 0; q < 16; q++) { accA[q] = 0ull; accB[q] = 0ull; }
        if (j < SEQ) { accum_half(accA, hb, wbm, s, cg, b0); dumpacc(part, accA, s, cg, b0); }
        if (j >= 1)    accum_half(accB, hb, wbm + 16 * RSTR, s, cg, b0);
        __syncthreads();                                   // S2: A partials ready, hbuf free

        if (j < SEQ) {
            float z0 = redcell(part, e0) + zxa0;
            float z1 = redcell(part, e1) + zxa1;
            zb[rc0 * 33 + rb0] = z0;
            zb[rc1 * 33 + rb1] = z1;
        }
        if (j >= 1) stage_h(hb, g_h1[rbuf], tid);
        __syncthreads();                                   // S3: zA ready, hbuf=h1 ready

        if (j < SEQ && tid < 128) {
            float zi = zb[(0  + gul) * 33 + gb];
            float zf = zb[(4  + gul) * 33 + gb];
            float zg = zb[(8  + gul) * 33 + gb];
            float zo = zb[(12 + gul) * 33 + gb];
            float ig = sigf(zi), fg = sigf(zf), gg = tanhfa(zg), og = sigf(zo);
            float cn = fg * g_c0[gidx] + ig * gg;
            float hn = og * tanhfa(cn);
            g_c0[gidx] = cn;
            g_h0[wb2][gidx] = hn;
        }
        if (j >= 1) { accum_half(accB, hb, wbm + 32 * RSTR, s, cg, b0); dumpacc(part, accB, s, cg, b0); }
        __syncthreads();                                   // S4: B partials ready

        if (j >= 1) {
            float z0 = redcell(part, e0) + biasB0;
            float z1 = redcell(part, e1) + biasB1;
            zb[rc0 * 33 + rb0] = z0;
            zb[rc1 * 33 + rb1] = z1;
        }
        __syncthreads();                                   // S5: zB ready

        if (j >= 1 && tid < 128) {
            float zi = zb[(0  + gul) * 33 + gb];
            float zf = zb[(4  + gul) * 33 + gb];
            float zg = zb[(8  + gul) * 33 + gb];
            float zo = zb[(12 + gul) * 33 + gb];
            float ig = sigf(zi), fg = sigf(zf), gg = tanhfa(zg), og = sigf(zo);
            float cn = fg * g_c1[gidx] + ig * gg;
            float hn = og * tanhfa(cn);
            g_c1[gidx] = cn;
            g_h1[wb2][gidx] = hn;
            out[(size_t)gb * SEQ * HID + (size_t)(j - 1) * HID + u0 + gul] = hn;
        }

        // ---- grid barrier ----
        __syncthreads();
        if (tid == 0) {
            __threadfence();
            atomicAdd(&g_count, 1u);
            const unsigned tgt = (unsigned)NCTA * (unsigned)(j + 1);
            while (*(volatile unsigned*)&g_count < tgt) __nanosleep(64);
            __threadfence();
        }
        __syncthreads();
    }
}

// ---------------- launch ----------------
extern "C" void kernel_launch(void* const* d_in, const int* in_sizes, int n_in,
                              void* d_out, int out_size) {
    const int*   src  = (const int*)  d_in[0];
    const float* emb  = (const float*)d_in[2];
    const float* Wk   = (const float*)d_in[3];
    const float* Wr   = (const float*)d_in[4];
    const float* bias = (const float*)d_in[5];
    float* out = (float*)d_out;
    float* out_emb = out + (size_t)BATCH * SEQ * HID;

    init_kernel<<<64, 256>>>();
    embed_kernel<<<BATCH * SEQ, 128>>>(src, emb, out_emb);
    gemm_zx0<<<dim3(G4 / 64, (BATCH * SEQ) / 128), 256>>>(out_emb, Wk, bias);

    cudaFuncSetAttribute(persist_kernel, cudaFuncAttributeMaxDynamicSharedMemorySize, 200000);
    persist_kernel<<<NCTA, TPB, 200000>>>(Wk, Wr, bias, out);
}

// round 4
// speedup vs baseline: 3.0542x; 1.0960x over previous
#include <cuda_runtime.h>

#define BATCH 32
#define SEQ   512
#define HID   512
#define G4    2048
#define NCTA  128
#define TPB   256

typedef unsigned long long u64;

// ---------------- static device scratch ----------------
__device__ float g_zx0[(size_t)BATCH * SEQ * G4];   // X @ Wk0 + b0
__device__ float g_h0[2][BATCH * HID];
__device__ float g_h1[2][BATCH * HID];
__device__ float g_c0[BATCH * HID];
__device__ float g_c1[BATCH * HID];
__device__ unsigned g_count;

// ---------------- packed f32x2 helpers ----------------
__device__ __forceinline__ u64 pk(float lo, float hi) {
    u64 r; asm("mov.b64 %0, {%1,%2};" : "=l"(r) : "f"(lo), "f"(hi)); return r;
}
__device__ __forceinline__ float2 upk(u64 v) {
    float2 r; asm("mov.b64 {%0,%1}, %2;" : "=f"(r.x), "=f"(r.y) : "l"(v)); return r;
}
__device__ __forceinline__ void fma2(u64 &acc, u64 a, u64 b) {
    asm("fma.rn.f32x2 %0, %1, %2, %0;" : "+l"(acc) : "l"(a), "l"(b));
}
__device__ __forceinline__ u64 add2(u64 a, u64 b) {
    u64 r; asm("add.rn.f32x2 %0, %1, %2;" : "=l"(r) : "l"(a), "l"(b)); return r;
}

__device__ __forceinline__ float sigf(float x)  { return 1.f / (1.f + __expf(-x)); }
__device__ __forceinline__ float tanhfa(float x){ return 2.f / (1.f + __expf(-2.f * x)) - 1.f; }

// ---------------- init ----------------
__global__ void init_kernel() {
    int i = blockIdx.x * blockDim.x + threadIdx.x;
    if (i == 0) g_count = 0u;
    if (i < BATCH * HID) {
        g_c0[i] = 0.f; g_c1[i] = 0.f;
        g_h0[0][i] = 0.f; g_h0[1][i] = 0.f;
        g_h1[0][i] = 0.f; g_h1[1][i] = 0.f;
    }
}

// ---------------- embedding gather ----------------
__global__ void embed_kernel(const int* __restrict__ src,
                             const float* __restrict__ emb,
                             float* __restrict__ oe) {
    int bs = blockIdx.x;
    int tok = src[bs];
    const float4* er = (const float4*)(emb + (size_t)tok * HID);
    float4* orow = (float4*)(oe + (size_t)bs * HID);
    orow[threadIdx.x] = er[threadIdx.x];
}

// ---------------- precompute GEMM: Zx0 = X @ Wk0 + b0 ----------------
__global__ __launch_bounds__(256) void gemm_zx0(const float* __restrict__ X,
                                                const float* __restrict__ Wk,
                                                const float* __restrict__ bias) {
    __shared__ float As[16][128];
    __shared__ float Bs[16][64];
    const int bm = blockIdx.y * 128;
    const int bn = blockIdx.x * 64;
    const int tid = threadIdx.x;
    const int tx = tid & 15, ty = tid >> 4;

    u64 acc[4][4];
#pragma unroll
    for (int p = 0; p < 4; p++)
#pragma unroll
        for (int q = 0; q < 4; q++) acc[p][q] = 0ull;

    for (int k0 = 0; k0 < 512; k0 += 16) {
#pragma unroll
        for (int r = 0; r < 2; r++) {
            int i = tid + 256 * r;
            int m = i >> 2, kq = (i & 3) * 4;
            float4 v = *(const float4*)(X + (size_t)(bm + m) * 512 + k0 + kq);
            As[kq + 0][m] = v.x; As[kq + 1][m] = v.y;
            As[kq + 2][m] = v.z; As[kq + 3][m] = v.w;
        }
        {
            int k = tid >> 4, n4 = (tid & 15) * 4;
            *(float4*)&Bs[k][n4] = *(const float4*)(Wk + (size_t)(k0 + k) * G4 + bn + n4);
        }
        __syncthreads();
#pragma unroll
        for (int kk = 0; kk < 16; kk++) {
            u64 a0 = *(const u64*)&As[kk][ty * 8 + 0];
            u64 a1 = *(const u64*)&As[kk][ty * 8 + 2];
            u64 a2 = *(const u64*)&As[kk][ty * 8 + 4];
            u64 a3 = *(const u64*)&As[kk][ty * 8 + 6];
            float4 bv = *(const float4*)&Bs[kk][tx * 4];
            u64 b0 = pk(bv.x, bv.x), b1 = pk(bv.y, bv.y);
            u64 b2 = pk(bv.z, bv.z), b3 = pk(bv.w, bv.w);
            fma2(acc[0][0], a0, b0); fma2(acc[0][1], a0, b1); fma2(acc[0][2], a0, b2); fma2(acc[0][3], a0, b3);
            fma2(acc[1][0], a1, b0); fma2(acc[1][1], a1, b1); fma2(acc[1][2], a1, b2); fma2(acc[1][3], a1, b3);
            fma2(acc[2][0], a2, b0); fma2(acc[2][1], a2, b1); fma2(acc[2][2], a2, b2); fma2(acc[2][3], a2, b3);
            fma2(acc[3][0], a3, b0); fma2(acc[3][1], a3, b1); fma2(acc[3][2], a3, b2); fma2(acc[3][3], a3, b3);
        }
        __syncthreads();
    }
#pragma unroll
    for (int p = 0; p < 4; p++) {
#pragma unroll
        for (int q = 0; q < 4; q++) {
            int m0 = bm + ty * 8 + 2 * p;
            int n = bn + tx * 4 + q;
            float bb = bias[n];
            float2 v = upk(acc[p][q]);
            g_zx0[(size_t)m0 * G4 + n]       = v.x + bb;
            g_zx0[(size_t)(m0 + 1) * G4 + n] = v.y + bb;
        }
    }
}

// ================= persistent recurrence =================
// smem float layout:
//   ws[3][128 chunks][16 cols][4]   : 3*8192 fl
//   hs[128 chunks][32 b (xor ch&7)][4] : 16384 fl
//   part u64[8 warps][544]          : 8704 fl
//   zb[16][33]                      : 528 fl
#define WS_FL   8192
#define HS_OFF  24576
#define PART_OFF 40960
#define ZB_OFF  49664
#define SMEM_FL 50192

// warp accumulates its 16-chunk k-segment of one matrix into acc[16]
__device__ __forceinline__ void accum16(u64* acc, const float* hs, const float* wsm,
                                        int wid, int cidx2, int bg) {
    const int ch0 = wid * 16;
#pragma unroll 4
    for (int t = 0; t < 16; t++) {
        const int ch = ch0 + t;
        const float* wp = wsm + ch * 64;
        const float* hp = hs + ch * 128;
        const int chx = ch & 7;
        ulonglong2 wa = *(const ulonglong2*)(wp + cidx2 * 4);
        ulonglong2 wb = *(const ulonglong2*)(wp + (cidx2 + 8) * 4);
#pragma unroll
        for (int bi = 0; bi < 8; bi++) {
            const int b = 4 * bi + bg;
            ulonglong2 h = *(const ulonglong2*)(hp + ((b ^ chx) * 4));
            fma2(acc[bi],     wa.x, h.x); fma2(acc[bi],     wa.y, h.y);
            fma2(acc[8 + bi], wb.x, h.x); fma2(acc[8 + bi], wb.y, h.y);
        }
    }
}

__device__ __forceinline__ void dumpacc(u64* part, const u64* acc,
                                        int wid, int cidx2, int bg) {
    u64* pw = part + wid * 544;
#pragma unroll
    for (int cc = 0; cc < 2; cc++) {
        const int ci = cidx2 + 8 * cc;
#pragma unroll
        for (int bi = 0; bi < 8; bi++) {
            const int si = (4 * bi + bg) * 16 + ci;
            pw[si + (si >> 4)] = acc[cc * 8 + bi];
        }
    }
}

__device__ __forceinline__ float redcell(const u64* part, int e) {
    const int si = (e & 31) * 16 + (e >> 5);
    const int p = si + (si >> 4);
    u64 r = add2(add2(add2(part[p], part[544 + p]), add2(part[2 * 544 + p], part[3 * 544 + p])),
                 add2(add2(part[4 * 544 + p], part[5 * 544 + p]), add2(part[6 * 544 + p], part[7 * 544 + p])));
    float2 v = upk(r);
    return v.x + v.y;
}

// coalesced global->smem h stage with xor swizzle
__device__ __forceinline__ void stage_h(float* hs, const float* __restrict__ src, int tid) {
    const int chl = tid & 31;       // chunk lane
    const int bb = tid >> 5;        // batch base (0..7)
#pragma unroll
    for (int i = 0; i < 4; i++) {
        const int ch = chl + 32 * i;
        const int chx = ch & 7;
#pragma unroll
        for (int jj = 0; jj < 4; jj++) {
            const int b = bb + 8 * jj;
            float4 v = *(const float4*)(src + b * HID + ch * 4);
            *(float4*)(hs + ch * 128 + ((b ^ chx) * 4)) = v;
        }
    }
}

__global__ __launch_bounds__(TPB) void persist_kernel(const float* __restrict__ Wk,
                                                      const float* __restrict__ Wr,
                                                      const float* __restrict__ bias,
                                                      float* __restrict__ out) {
    extern __shared__ float smf[];
    float* ws0 = smf;
    float* ws1 = smf + WS_FL;
    float* ws2 = smf + 2 * WS_FL;
    float* hs  = smf + HS_OFF;
    u64*  part = (u64*)(smf + PART_OFF);
    float* zb  = smf + ZB_OFF;

    const int tid = threadIdx.x;
    const int cid = blockIdx.x;
    const int u0 = cid * 4;
    const int wid = tid >> 5;
    const int lane = tid & 31;
    const int cidx2 = lane & 7;
    const int bg = lane >> 3;

    // ---- load weight slices once into chunk-major layout ----
    {
        const float* wsrcs[3] = { Wr, Wk + (size_t)HID * G4, Wr + (size_t)HID * G4 };
        float* wdsts[3] = { ws0, ws1, ws2 };
#pragma unroll
        for (int m = 0; m < 3; m++) {
            const float* srcm = wsrcs[m];
            float* dst = wdsts[m];
            for (int i = 0; i < 8; i++) {
                int t2 = tid + TPB * i;           // 2048 iters: k(512) x g(4)
                int g = t2 & 3, k = t2 >> 2;
                float4 v = *(const float4*)(srcm + (size_t)k * G4 + g * HID + u0);
                int ch = k >> 2, kk = k & 3;
                float* d = dst + ch * 64 + (g * 4) * 4 + kk;
                d[0]  = v.x;   // ci = g*4+0
                d[4]  = v.y;   // ci = g*4+1
                d[8]  = v.z;
                d[12] = v.w;
            }
        }
    }

    // reducer constants (cells e0 = tid, e1 = tid + 256; cell = ci*32 + b)
    const int e0 = tid, e1 = tid + 256;
    const int rc0 = e0 >> 5, rb0 = e0 & 31;
    const int rc1 = e1 >> 5, rb1 = e1 & 31;
    const int col0 = (rc0 >> 2) * HID + u0 + (rc0 & 3);
    const int col1 = (rc1 >> 2) * HID + u0 + (rc1 & 3);
    const float biasB0 = bias[G4 + col0];
    const float biasB1 = bias[G4 + col1];
    // gate-thread constants
    const int gb = tid & 31, gul = (tid >> 5) & 3;
    const int gidx = gb * HID + u0 + gul;
    __syncthreads();

    for (int j = 0; j <= SEQ; j++) {
        const int rbuf = j & 1, wb2 = rbuf ^ 1;

        float zxa0 = 0.f, zxa1 = 0.f;
        if (j < SEQ) {
            zxa0 = g_zx0[((size_t)(rb0 * SEQ + j)) * G4 + col0];
            zxa1 = g_zx0[((size_t)(rb1 * SEQ + j)) * G4 + col1];
            stage_h(hs, g_h0[rbuf], tid);
        } else {
            stage_h(hs, g_h0[rbuf], tid);   // h0 still needed by layer1 (j>=1 path)
        }
        __syncthreads();                                   // S1: hs = h0

        u64 accA[16], accB[16];
#pragma unroll
        for (int q = 0; q < 16; q++) { accA[q] = 0ull; accB[q] = 0ull; }
        if (j < SEQ) { accum16(accA, hs, ws0, wid, cidx2, bg); dumpacc(part, accA, wid, cidx2, bg); }
        if (j >= 1)    accum16(accB, hs, ws1, wid, cidx2, bg);   // Wk1 . h0
        __syncthreads();                                   // S2: A partials ready, hs free

        if (j < SEQ) {
            float z0 = redcell(part, e0) + zxa0;
            float z1 = redcell(part, e1) + zxa1;
            zb[rc0 * 33 + rb0] = z0;
            zb[rc1 * 33 + rb1] = z1;
        }
        if (j >= 1) stage_h(hs, g_h1[rbuf], tid);
        __syncthreads();                                   // S3: zA ready, hs = h1

        if (j < SEQ && tid < 128) {
            float zi = zb[(0  + gul) * 33 + gb];
            float zf = zb[(4  + gul) * 33 + gb];
            float zg = zb[(8  + gul) * 33 + gb];
            float zo = zb[(12 + gul) * 33 + gb];
            float ig = sigf(zi), fg = sigf(zf), gg = tanhfa(zg), og = sigf(zo);
            float cn = fg * g_c0[gidx] + ig * gg;
            float hn = og * tanhfa(cn);
            g_c0[gidx] = cn;
            g_h0[wb2][gidx] = hn;
        }
        if (j >= 1) { accum16(accB, hs, ws2, wid, cidx2, bg); dumpacc(part, accB, wid, cidx2, bg); }
        __syncthreads();                                   // S4: B partials ready

        if (j >= 1) {
            float z0 = redcell(part, e0) + biasB0;
            float z1 = redcell(part, e1) + biasB1;
            zb[rc0 * 33 + rb0] = z0;
            zb[rc1 * 33 + rb1] = z1;
        }
        __syncthreads();                                   // S5: zB ready

        if (j >= 1 && tid < 128) {
            float zi = zb[(0  + gul) * 33 + gb];
            float zf = zb[(4  + gul) * 33 + gb];
            float zg = zb[(8  + gul) * 33 + gb];
            float zo = zb[(12 + gul) * 33 + gb];
            float ig = sigf(zi), fg = sigf(zf), gg = tanhfa(zg), og = sigf(zo);
            float cn = fg * g_c1[gidx] + ig * gg;
            float hn = og * tanhfa(cn);
            g_c1[gidx] = cn;
            g_h1[wb2][gidx] = hn;
            out[(size_t)gb * SEQ * HID + (size_t)(j - 1) * HID + u0 + gul] = hn;
        }

        // ---- grid barrier (RED arrive + single-thread poll) ----
        __syncthreads();
        if (tid == 0) {
            __threadfence();
            atomicAdd(&g_count, 1u);                       // no return use -> RED
            const unsigned tgt = (unsigned)NCTA * (unsigned)(j + 1);
            while (*(volatile unsigned*)&g_count < tgt) __nanosleep(32);
            __threadfence();
        }
        __syncthreads();
    }
}

// ---------------- launch ----------------
extern "C" void kernel_launch(void* const* d_in, const int* in_sizes, int n_in,
                              void* d_out, int out_size) {
    const int*   src  = (const int*)  d_in[0];
    const float* emb  = (const float*)d_in[2];
    const float* Wk   = (const float*)d_in[3];
    const float* Wr   = (const float*)d_in[4];
    const float* bias = (const float*)d_in[5];
    float* out = (float*)d_out;
    float* out_emb = out + (size_t)BATCH * SEQ * HID;

    init_kernel<<<64, 256>>>();
    embed_kernel<<<BATCH * SEQ, 128>>>(src, emb, out_emb);
    gemm_zx0<<<dim3(G4 / 64, (BATCH * SEQ) / 128), 256>>>(out_emb, Wk, bias);

    cudaFuncSetAttribute(persist_kernel, cudaFuncAttributeMaxDynamicSharedMemorySize, SMEM_FL * 4);
    persist_kernel<<<NCTA, TPB, SMEM_FL * 4>>>(Wk, Wr, bias, out);
}